// round 15
// baseline (speedup 1.0000x reference)
#include <cuda_runtime.h>
#include <cstdint>
#include <cstddef>

#define BSZ 32
#define SEQ 512
#define IND 512
#define HID 1024
#define G4  4096
#define NBLK 128

// ---------------- device globals ----------------
__device__ float g_xU[(size_t)BSZ * SEQ * G4];     // [b*512+t][4096]
__device__ float g_Xc[(size_t)BSZ * SEQ * IND];    // tf32-rounded x
__device__ float g_Uc[(size_t)IND * G4];           // tf32 U concat [k][4096]
__device__ float g_bc[G4];                          // bias concat
__device__ float g_Vf[(size_t)NBLK * 32768];       // V fragments per block (R7 packing)
__device__ float g_hA[2][NBLK * 256];              // h in A-fragment order, parity t&1
__device__ volatile int g_cnt[NBLK];               // completed steps per block

// ---------------- helpers ----------------
__device__ __forceinline__ uint32_t smem_u32(const void* p) {
    uint32_t a;
    asm("{ .reg .u64 t; cvta.to.shared.u64 t, %1; cvt.u32.u64 %0, t; }" : "=r"(a) : "l"(p));
    return a;
}
__device__ __forceinline__ void cp_async16(uint32_t dst, const void* src) {
    asm volatile("cp.async.cg.shared.global [%0], [%1], 16;" :: "r"(dst), "l"(src));
}
__device__ __forceinline__ void cp_commit() { asm volatile("cp.async.commit_group;" ::: "memory"); }
template <int N> __device__ __forceinline__ void cp_wait() {
    asm volatile("cp.async.wait_group %0;" :: "n"(N) : "memory");
}
__device__ __forceinline__ float to_tf32(float x) {
    uint32_t r;
    asm("cvt.rna.tf32.f32 %0, %1;" : "=r"(r) : "f"(x));
    return __uint_as_float(r);
}
__device__ __forceinline__ void mma8(float& d0, float& d1, float& d2, float& d3,
                                     uint32_t a0, uint32_t a1, uint32_t a2, uint32_t a3,
                                     uint32_t b0, uint32_t b1) {
    asm volatile("mma.sync.aligned.m16n8k8.row.col.f32.tf32.tf32.f32 "
                 "{%0,%1,%2,%3}, {%4,%5,%6,%7}, {%8,%9}, {%0,%1,%2,%3};"
                 : "+f"(d0), "+f"(d1), "+f"(d2), "+f"(d3)
                 : "r"(a0), "r"(a1), "r"(a2), "r"(a3), "r"(b0), "r"(b1));
}
__device__ __forceinline__ float sigmoid_f(float x) { return 1.f / (1.f + __expf(-x)); }
__device__ __forceinline__ float tanh_f(float x) { return 1.f - 2.f / (__expf(2.f * x) + 1.f); }

// ---------------- fused prep kernel (K12 verbatim) ----------------
__global__ __launch_bounds__(256) void prep(
    const float* __restrict__ x,
    const float* __restrict__ Uf, const float* __restrict__ Ui,
    const float* __restrict__ Uo, const float* __restrict__ Ug,
    const float* __restrict__ Vf, const float* __restrict__ Vi,
    const float* __restrict__ Vo, const float* __restrict__ Vg,
    const float* __restrict__ bf, const float* __restrict__ bi,
    const float* __restrict__ bo, const float* __restrict__ bg)
{
    const int b = blockIdx.x, tid = threadIdx.x;
    if (b < 256) {
        const size_t base = (size_t)b * 65536;
        for (int i = tid; i < 65536; i += 256) g_Xc[base + i] = to_tf32(x[base + i]);
    } else if (b < 288) {
        const int bb = b - 256;
        const size_t base = (size_t)bb * 65536;
        for (int i = tid; i < 65536; i += 256) {
            size_t idx = base + i;
            int k = (int)(idx >> 12), col = (int)(idx & 4095);
            int g = col >> 10, u = col & 1023;
            const float* U = (g == 0) ? Uf : (g == 1) ? Ui : (g == 2) ? Uo : Ug;
            g_Uc[idx] = to_tf32(U[(size_t)k * HID + u]);
        }
        if (bb == 0) {
            for (int i = tid; i < G4; i += 256) {
                int g = i >> 10, u = i & 1023;
                const float* bv = (g == 0) ? bf : (g == 1) ? bi : (g == 2) ? bo : bg;
                g_bc[i] = bv[u];
            }
        }
    } else {
        const int bid = b - 288;  // 0..127
        float* dst = g_Vf + (size_t)bid * 32768;
        for (int e = tid; e < 32768; e += 256) {
            int wd = e & 1, lane = (e >> 1) & 31, nt = (e >> 6) & 3, ks = e >> 8;
            int k = ks * 8 + (lane & 3) + wd * 4;
            int c = nt * 8 + (lane >> 2);
            int u = c >> 2, g = c & 3;
            const float* V = (g == 0) ? Vf : (g == 1) ? Vi : (g == 2) ? Vo : Vg;
            dst[e] = to_tf32(V[(size_t)k * HID + bid * 8 + u]);
        }
    }
}

// ---------------- Phase A: mma.sync tf32 GEMM (K12 verbatim) ----------------
#define PA_SA0 0
#define PA_SA1 18432
#define PA_SB0 36864
#define PA_SB1 53760
#define PA_SMEM 70656

__global__ __launch_bounds__(256) void gemm_xU_mma() {
    extern __shared__ char smx[];
    const uint32_t sb = smem_u32(smx);
    const int tid = threadIdx.x;
    const int n0 = blockIdx.x * 128, m0 = blockIdx.y * 128;
    const int w = tid >> 5, l = tid & 31;
    const int wm = w >> 2, wn = w & 3;

    float acc[4][4][4];
    #pragma unroll
    for (int i = 0; i < 4; ++i)
        #pragma unroll
        for (int j = 0; j < 4; ++j)
            #pragma unroll
            for (int r = 0; r < 4; ++r) acc[i][j][r] = 0.f;

    auto stage = [&](int c) {
        const uint32_t sa = sb + ((c & 1) ? PA_SA1 : PA_SA0);
        const uint32_t sbm = sb + ((c & 1) ? PA_SB1 : PA_SB0);
        #pragma unroll
        for (int i = 0; i < 4; ++i) {
            int e = tid + i * 256;
            int r = e >> 3, kq = e & 7;
            cp_async16(sa + (uint32_t)(r * 144 + kq * 16),
                       g_Xc + (size_t)(m0 + r) * IND + c * 32 + kq * 4);
        }
        #pragma unroll
        for (int i = 0; i < 4; ++i) {
            int e = tid + i * 256;
            int r = e >> 5, nq = e & 31;
            cp_async16(sbm + (uint32_t)(r * 528 + nq * 16),
                       g_Uc + (size_t)(c * 32 + r) * G4 + n0 + nq * 4);
        }
    };

    stage(0); cp_commit();
    #pragma unroll 1
    for (int c = 0; c < 16; ++c) {
        __syncthreads();
        if (c < 15) { stage(c + 1); cp_commit(); cp_wait<1>(); }
        else cp_wait<0>();
        __syncthreads();
        const uint32_t* As = (const uint32_t*)(smx + ((c & 1) ? PA_SA1 : PA_SA0));
        const uint32_t* Bs = (const uint32_t*)(smx + ((c & 1) ? PA_SB1 : PA_SB0));
        #pragma unroll
        for (int kk = 0; kk < 32; kk += 8) {
            uint32_t a[4][4];
            #pragma unroll
            for (int mt = 0; mt < 4; ++mt) {
                int r = wm * 64 + mt * 16 + (l >> 2);
                a[mt][0] = As[r * 36 + kk + (l & 3)];
                a[mt][1] = As[(r + 8) * 36 + kk + (l & 3)];
                a[mt][2] = As[r * 36 + kk + 4 + (l & 3)];
                a[mt][3] = As[(r + 8) * 36 + kk + 4 + (l & 3)];
            }
            #pragma unroll
            for (int nt = 0; nt < 4; ++nt) {
                int n = wn * 32 + nt * 8 + (l >> 2);
                uint32_t b0 = Bs[(kk + (l & 3)) * 132 + n];
                uint32_t b1 = Bs[(kk + 4 + (l & 3)) * 132 + n];
                #pragma unroll
                for (int mt = 0; mt < 4; ++mt)
                    mma8(acc[mt][nt][0], acc[mt][nt][1], acc[mt][nt][2], acc[mt][nt][3],
                         a[mt][0], a[mt][1], a[mt][2], a[mt][3], b0, b1);
            }
        }
    }
    #pragma unroll
    for (int mt = 0; mt < 4; ++mt) {
        #pragma unroll
        for (int nt = 0; nt < 4; ++nt) {
            int m = m0 + wm * 64 + mt * 16 + (l >> 2);
            int n = n0 + wn * 32 + nt * 8 + (l & 3) * 2;
            float2 bv = *(const float2*)&g_bc[n];
            float2 v0 = make_float2(acc[mt][nt][0] + bv.x, acc[mt][nt][1] + bv.y);
            float2 v1 = make_float2(acc[mt][nt][2] + bv.x, acc[mt][nt][3] + bv.y);
            *(float2*)&g_xU[(size_t)m * G4 + n] = v0;
            *(float2*)&g_xU[(size_t)(m + 8) * G4 + n] = v1;
        }
    }
}

// ---------------- Phase B: persistent mma.sync recurrence ----------------
// K12 chunking (8 x 16KB, 16-producer deps) with a triple-buffer depth-2
// pipeline: ONE __syncthreads per chunk (8/step instead of 16).
// Warps: 8 kg x 2 batch-half; each A fragment loaded once per warp.
// smem: Vf 128KB | hbuf 3x16KB | gpart 8x32x36 (36864B) = 217088B
#define SM_HB 131072
#define SM_GP (131072 + 49152)
#define SMEM_B_BYTES (SM_GP + 36864)

__global__ __launch_bounds__(512) void lstm_mma(float* __restrict__ hseq,
                                                float* __restrict__ hlast)
{
    extern __shared__ char smx[];
    const uint32_t sb = smem_u32(smx);
    float* Vfs = (float*)smx;
    float* gpart = (float*)(smx + SM_GP);
    const int tid = threadIdx.x, bid = blockIdx.x;
    const int hbase = bid * 8;

    {
        const float4* src = (const float4*)(g_Vf + (size_t)bid * 32768);
        float4* dst = (float4*)smx;
        for (int i = tid; i < 8192; i += 512) dst[i] = src[i];
    }
    for (int i = tid; i < 9216; i += 512) gpart[i] = 0.f;
    __syncthreads();

    const int w = tid >> 5, l = tid & 31;
    const int kg = w >> 1, bh = w & 1;       // K-group 0..7, batch-half 0..1
    const int pb = tid >> 3, pu = tid & 7;   // pointwise mapping (tid < 256)
    float cr = 0.f;

    for (int t = 0; t < SEQ; ++t) {
        float xg0 = 0.f, xg1 = 0.f, xg2 = 0.f, xg3 = 0.f;
        if (tid < 256) {
            const float* xrow = g_xU + ((size_t)pb * SEQ + t) * G4 + hbase + pu;
            xg0 = __ldg(xrow);
            xg1 = __ldg(xrow + HID);
            xg2 = __ldg(xrow + 2 * HID);
            xg3 = __ldg(xrow + 3 * HID);
        }

        if (t > 0) {
            float acc[4][4];
            #pragma unroll
            for (int i = 0; i < 4; ++i)
                #pragma unroll
                for (int r = 0; r < 4; ++r) acc[i][r] = 0.f;

            const float4* hsrc = (const float4*)(g_hA[(t + 1) & 1]);

            // stage 16KB chunk into buf; lanes 0-1 poll the 2 producer blocks
            // whose fragment region this warp copies (K12 verbatim).
            auto stageH = [&](int chunk, int buf) {
                if (l < 2) {
                    volatile int* cp = g_cnt + chunk * 16 + (w >> 1) + l * 8;
                    while (*cp < t) { }
                }
                __syncwarp();
                const uint32_t d = sb + SM_HB + (uint32_t)buf * 16384u;
                cp_async16(d + (uint32_t)tid * 16u, hsrc + chunk * 1024 + tid);
                cp_async16(d + (uint32_t)(tid + 512) * 16u,
                           hsrc + chunk * 1024 + tid + 512);
            };

            // depth-2 prologue
            stageH(bid & 7, 0); cp_commit();
            stageH((bid + 1) & 7, 1); cp_commit();

            #pragma unroll 1
            for (int i = 0; i < 8; ++i) {
                const int chunk = (i + bid) & 7;
                if (i < 7) cp_wait<1>(); else cp_wait<0>();
                __syncthreads();   // chunk i visible + buf (i+2)%3 free
                if (i + 2 < 8) { stageH((i + 2 + bid) & 7, (i + 2) % 3); cp_commit(); }

                const float4* hb = (const float4*)(smx + SM_HB + (i % 3) * 16384);
                #pragma unroll
                for (int e = 0; e < 2; ++e) {
                    int ksl = kg * 2 + e;
                    float4 A = hb[ksl * 64 + bh * 32 + l];
                    uint32_t a0 = __float_as_uint(A.x), a1 = __float_as_uint(A.y);
                    uint32_t a2 = __float_as_uint(A.z), a3 = __float_as_uint(A.w);
                    int ks = chunk * 16 + ksl;
                    #pragma unroll
                    for (int nt2 = 0; nt2 < 4; ++nt2) {
                        float2 Bv = *(const float2*)(
                            Vfs + ((size_t)(ks * 4 + nt2) * 32 + l) * 2);
                        uint32_t b0 = __float_as_uint(Bv.x);
                        uint32_t b1 = __float_as_uint(Bv.y);
                        mma8(acc[nt2][0], acc[nt2][1], acc[nt2][2], acc[nt2][3],
                             a0, a1, a2, a3, b0, b1);
                    }
                }
            }
            // partials -> gpart[kg][batch-half bh]
            int r0 = l >> 2;
            float* gp = gpart + kg * 1152 + bh * 576;   // bh*16*36
            #pragma unroll
            for (int nt2 = 0; nt2 < 4; ++nt2) {
                int cb = nt2 * 8 + (l & 3) * 2;
                *(float2*)&gp[r0 * 36 + cb]       = make_float2(acc[nt2][0], acc[nt2][1]);
                *(float2*)&gp[(r0 + 8) * 36 + cb] = make_float2(acc[nt2][2], acc[nt2][3]);
            }
        }
        __syncthreads();

        // overwrite-guard: h(t) replaces h(t-2); all blocks must be >= t.
        // Poll overlaps with gate math below.
        if (tid >= 256 && tid < 256 + NBLK) {
            volatile int* cp = g_cnt + (tid - 256);
            while (*cp < t) __nanosleep(16);
        }

        float hval = 0.f;
        if (tid < 256) {
            float g0 = xg0, g1 = xg1, g2 = xg2, g3 = xg3;
            #pragma unroll
            for (int ks = 0; ks < 8; ++ks) {
                float4 p = *(const float4*)&gpart[ks * 1152 + pb * 36 + pu * 4];
                g0 += p.x; g1 += p.y; g2 += p.z; g3 += p.w;
            }
            float fg = sigmoid_f(g0), ig = sigmoid_f(g1);
            float og = sigmoid_f(g2), gg = tanh_f(g3);
            cr = fg * cr + ig * gg;
            hval = og * tanh_f(cr);
        }
        __syncthreads();   // guard satisfied by all pollers

        if (tid < 256) {
            int mt = pb >> 4, br = pb & 15;
            int lane = (br & 7) * 4 + (pu & 3);
            int wd = (pu < 4) ? ((br & 8) ? 1 : 0) : ((br & 8) ? 3 : 2);
            g_hA[t & 1][((bid * 2 + mt) * 32 + lane) * 4 + wd] = to_tf32(hval);
        }
        __syncthreads();
        if (tid == 0) {
            __threadfence();          // single fence orders the block's writes
            g_cnt[bid] = t + 1;       // publish: h(t) visible
        }

        // deferred (off critical path) output writes
        if (tid < 256) {
            hseq[((size_t)pb * SEQ + t) * HID + hbase + pu] = hval;
            if (t == SEQ - 1) hlast[(size_t)pb * HID + hbase + pu] = hval;
        }
    }
}

// ---------------- launch ----------------
extern "C" void kernel_launch(void* const* d_in, const int* in_sizes, int n_in,
                              void* d_out, int out_size)
{
    const float* x  = (const float*)d_in[0];
    const float* Uf = (const float*)d_in[1];
    const float* Vf = (const float*)d_in[2];
    const float* bf = (const float*)d_in[3];
    const float* Ui = (const float*)d_in[4];
    const float* Vi = (const float*)d_in[5];
    const float* bi = (const float*)d_in[6];
    const float* Uo = (const float*)d_in[7];
    const float* Vo = (const float*)d_in[8];
    const float* bo = (const float*)d_in[9];
    const float* Ug = (const float*)d_in[10];
    const float* Vg = (const float*)d_in[11];
    const float* bg = (const float*)d_in[12];

    float* out   = (float*)d_out;
    float* hlast = out;                 // [32][1024]
    float* hseq  = out + BSZ * HID;     // [32][512][1024]

    void* cn = nullptr;
    cudaGetSymbolAddress(&cn, g_cnt);
    cudaMemsetAsync(cn, 0, NBLK * sizeof(int), 0);

    cudaFuncSetAttribute(gemm_xU_mma, cudaFuncAttributeMaxDynamicSharedMemorySize, PA_SMEM);
    cudaFuncSetAttribute(lstm_mma, cudaFuncAttributeMaxDynamicSharedMemorySize, SMEM_B_BYTES);

    prep<<<416, 256>>>(x, Uf, Ui, Uo, Ug, Vf, Vi, Vo, Vg, bf, bi, bo, bg);
    dim3 ggrid(G4 / 128, (BSZ * SEQ) / 128);   // (32, 128)
    gemm_xU_mma<<<ggrid, 256, PA_SMEM>>>();
    lstm_mma<<<NBLK, 512, SMEM_B_BYTES>>>(hseq, hlast);
}

// round 17
// speedup vs baseline: 1.3325x; 1.3325x over previous
#include <cuda_runtime.h>
#include <cstdint>
#include <cstddef>

#define BSZ 32
#define SEQ 512
#define IND 512
#define HID 1024
#define G4  4096
#define NBLK 128

// ---------------- device globals ----------------
__device__ float g_xU[(size_t)BSZ * SEQ * G4];     // [b*512+t][4096]
__device__ float g_Xc[(size_t)BSZ * SEQ * IND];    // tf32-rounded x
__device__ float g_Uc[(size_t)IND * G4];           // tf32 U concat [k][4096]
__device__ float g_bc[G4];                          // bias concat
__device__ float g_Vf[(size_t)NBLK * 32768];       // V fragments per block (R7 packing)
__device__ float g_hA[2][NBLK * 256];              // h in A-fragment order, parity t&1
__device__ volatile int g_cnt[NBLK];               // completed steps per block

// ---------------- helpers ----------------
__device__ __forceinline__ uint32_t smem_u32(const void* p) {
    uint32_t a;
    asm("{ .reg .u64 t; cvta.to.shared.u64 t, %1; cvt.u32.u64 %0, t; }" : "=r"(a) : "l"(p));
    return a;
}
__device__ __forceinline__ void cp_async16(uint32_t dst, const void* src) {
    asm volatile("cp.async.cg.shared.global [%0], [%1], 16;" :: "r"(dst), "l"(src));
}
__device__ __forceinline__ void cp_commit() { asm volatile("cp.async.commit_group;" ::: "memory"); }
template <int N> __device__ __forceinline__ void cp_wait() {
    asm volatile("cp.async.wait_group %0;" :: "n"(N) : "memory");
}
__device__ __forceinline__ float to_tf32(float x) {
    uint32_t r;
    asm("cvt.rna.tf32.f32 %0, %1;" : "=r"(r) : "f"(x));
    return __uint_as_float(r);
}
__device__ __forceinline__ void mma8(float& d0, float& d1, float& d2, float& d3,
                                     uint32_t a0, uint32_t a1, uint32_t a2, uint32_t a3,
                                     uint32_t b0, uint32_t b1) {
    asm volatile("mma.sync.aligned.m16n8k8.row.col.f32.tf32.tf32.f32 "
                 "{%0,%1,%2,%3}, {%4,%5,%6,%7}, {%8,%9}, {%0,%1,%2,%3};"
                 : "+f"(d0), "+f"(d1), "+f"(d2), "+f"(d3)
                 : "r"(a0), "r"(a1), "r"(a2), "r"(a3), "r"(b0), "r"(b1));
}
__device__ __forceinline__ float sigmoid_f(float x) { return 1.f / (1.f + __expf(-x)); }
__device__ __forceinline__ float tanh_f(float x) { return 1.f - 2.f / (__expf(2.f * x) + 1.f); }

// ---------------- fused prep kernel (K12 verbatim) ----------------
__global__ __launch_bounds__(256) void prep(
    const float* __restrict__ x,
    const float* __restrict__ Uf, const float* __restrict__ Ui,
    const float* __restrict__ Uo, const float* __restrict__ Ug,
    const float* __restrict__ Vf, const float* __restrict__ Vi,
    const float* __restrict__ Vo, const float* __restrict__ Vg,
    const float* __restrict__ bf, const float* __restrict__ bi,
    const float* __restrict__ bo, const float* __restrict__ bg)
{
    const int b = blockIdx.x, tid = threadIdx.x;
    if (b < 256) {
        const size_t base = (size_t)b * 65536;
        for (int i = tid; i < 65536; i += 256) g_Xc[base + i] = to_tf32(x[base + i]);
    } else if (b < 288) {
        const int bb = b - 256;
        const size_t base = (size_t)bb * 65536;
        for (int i = tid; i < 65536; i += 256) {
            size_t idx = base + i;
            int k = (int)(idx >> 12), col = (int)(idx & 4095);
            int g = col >> 10, u = col & 1023;
            const float* U = (g == 0) ? Uf : (g == 1) ? Ui : (g == 2) ? Uo : Ug;
            g_Uc[idx] = to_tf32(U[(size_t)k * HID + u]);
        }
        if (bb == 0) {
            for (int i = tid; i < G4; i += 256) {
                int g = i >> 10, u = i & 1023;
                const float* bv = (g == 0) ? bf : (g == 1) ? bi : (g == 2) ? bo : bg;
                g_bc[i] = bv[u];
            }
        }
    } else {
        const int bid = b - 288;  // 0..127
        float* dst = g_Vf + (size_t)bid * 32768;
        for (int e = tid; e < 32768; e += 256) {
            int wd = e & 1, lane = (e >> 1) & 31, nt = (e >> 6) & 3, ks = e >> 8;
            int k = ks * 8 + (lane & 3) + wd * 4;
            int c = nt * 8 + (lane >> 2);
            int u = c >> 2, g = c & 3;
            const float* V = (g == 0) ? Vf : (g == 1) ? Vi : (g == 2) ? Vo : Vg;
            dst[e] = to_tf32(V[(size_t)k * HID + bid * 8 + u]);
        }
    }
}

// ---------------- Phase A: mma.sync tf32 GEMM ----------------
// K12 structure; Bs row stride padded 132 -> 136 floats (136 % 32 == 8)
// so B-fragment LDS.64 reads are bank-conflict-free.
#define PA_SA0 0
#define PA_SA1 18432
#define PA_SB0 36864
#define PA_SB1 54272
#define PA_SMEM 71680

__global__ __launch_bounds__(256) void gemm_xU_mma() {
    extern __shared__ char smx[];
    const uint32_t sb = smem_u32(smx);
    const int tid = threadIdx.x;
    const int n0 = blockIdx.x * 128, m0 = blockIdx.y * 128;
    const int w = tid >> 5, l = tid & 31;
    const int wm = w >> 2, wn = w & 3;

    float acc[4][4][4];
    #pragma unroll
    for (int i = 0; i < 4; ++i)
        #pragma unroll
        for (int j = 0; j < 4; ++j)
            #pragma unroll
            for (int r = 0; r < 4; ++r) acc[i][j][r] = 0.f;

    auto stage = [&](int c) {
        const uint32_t sa = sb + ((c & 1) ? PA_SA1 : PA_SA0);
        const uint32_t sbm = sb + ((c & 1) ? PA_SB1 : PA_SB0);
        #pragma unroll
        for (int i = 0; i < 4; ++i) {
            int e = tid + i * 256;
            int r = e >> 3, kq = e & 7;
            cp_async16(sa + (uint32_t)(r * 144 + kq * 16),
                       g_Xc + (size_t)(m0 + r) * IND + c * 32 + kq * 4);
        }
        #pragma unroll
        for (int i = 0; i < 4; ++i) {
            int e = tid + i * 256;
            int r = e >> 5, nq = e & 31;
            cp_async16(sbm + (uint32_t)(r * 544 + nq * 16),
                       g_Uc + (size_t)(c * 32 + r) * G4 + n0 + nq * 4);
        }
    };

    stage(0); cp_commit();
    #pragma unroll 1
    for (int c = 0; c < 16; ++c) {
        __syncthreads();
        if (c < 15) { stage(c + 1); cp_commit(); cp_wait<1>(); }
        else cp_wait<0>();
        __syncthreads();
        const uint32_t* As = (const uint32_t*)(smx + ((c & 1) ? PA_SA1 : PA_SA0));
        const uint32_t* Bs = (const uint32_t*)(smx + ((c & 1) ? PA_SB1 : PA_SB0));
        #pragma unroll
        for (int kk = 0; kk < 32; kk += 8) {
            uint32_t a[4][4];
            #pragma unroll
            for (int mt = 0; mt < 4; ++mt) {
                int r = wm * 64 + mt * 16 + (l >> 2);
                a[mt][0] = As[r * 36 + kk + (l & 3)];
                a[mt][1] = As[(r + 8) * 36 + kk + (l & 3)];
                a[mt][2] = As[r * 36 + kk + 4 + (l & 3)];
                a[mt][3] = As[(r + 8) * 36 + kk + 4 + (l & 3)];
            }
            #pragma unroll
            for (int nt = 0; nt < 4; ++nt) {
                int n = wn * 32 + nt * 8 + (l >> 2);
                uint32_t b0 = Bs[(kk + (l & 3)) * 136 + n];
                uint32_t b1 = Bs[(kk + 4 + (l & 3)) * 136 + n];
                #pragma unroll
                for (int mt = 0; mt < 4; ++mt)
                    mma8(acc[mt][nt][0], acc[mt][nt][1], acc[mt][nt][2], acc[mt][nt][3],
                         a[mt][0], a[mt][1], a[mt][2], a[mt][3], b0, b1);
            }
        }
    }
    #pragma unroll
    for (int mt = 0; mt < 4; ++mt) {
        #pragma unroll
        for (int nt = 0; nt < 4; ++nt) {
            int m = m0 + wm * 64 + mt * 16 + (l >> 2);
            int n = n0 + wn * 32 + nt * 8 + (l & 3) * 2;
            float2 bv = *(const float2*)&g_bc[n];
            float2 v0 = make_float2(acc[mt][nt][0] + bv.x, acc[mt][nt][1] + bv.y);
            float2 v1 = make_float2(acc[mt][nt][2] + bv.x, acc[mt][nt][3] + bv.y);
            *(float2*)&g_xU[(size_t)m * G4 + n] = v0;
            *(float2*)&g_xU[(size_t)(m + 8) * G4 + n] = v1;
        }
    }
}

// ---------------- Phase B: persistent mma.sync recurrence (K12 verbatim) ----
// 8 x 16KB chunks, double-buffered, 2 syncs/chunk; warps 8 kg x 2 batch-half;
// each A fragment loaded once per warp; producer-group dataflow sync.
// smem: Vf 128KB | hbuf 2x16KB | gpart 8x32x36 (36864B) = 200704B
#define SM_HB 131072
#define SM_GP 163840
#define SMEM_B_BYTES (163840 + 36864)

__global__ __launch_bounds__(512) void lstm_mma(float* __restrict__ hseq,
                                                float* __restrict__ hlast)
{
    extern __shared__ char smx[];
    const uint32_t sb = smem_u32(smx);
    float* Vfs = (float*)smx;
    float* gpart = (float*)(smx + SM_GP);
    const int tid = threadIdx.x, bid = blockIdx.x;
    const int hbase = bid * 8;

    {
        const float4* src = (const float4*)(g_Vf + (size_t)bid * 32768);
        float4* dst = (float4*)smx;
        for (int i = tid; i < 8192; i += 512) dst[i] = src[i];
    }
    for (int i = tid; i < 9216; i += 512) gpart[i] = 0.f;
    __syncthreads();

    const int w = tid >> 5, l = tid & 31;
    const int kg = w >> 1, bh = w & 1;       // K-group 0..7, batch-half 0..1
    const int pb = tid >> 3, pu = tid & 7;   // pointwise mapping (tid < 256)
    float cr = 0.f;

    for (int t = 0; t < SEQ; ++t) {
        float xg0 = 0.f, xg1 = 0.f, xg2 = 0.f, xg3 = 0.f;
        if (tid < 256) {
            const float* xrow = g_xU + ((size_t)pb * SEQ + t) * G4 + hbase + pu;
            xg0 = __ldg(xrow);
            xg1 = __ldg(xrow + HID);
            xg2 = __ldg(xrow + 2 * HID);
            xg3 = __ldg(xrow + 3 * HID);
        }

        if (t > 0) {
            float acc[4][4];
            #pragma unroll
            for (int i = 0; i < 4; ++i)
                #pragma unroll
                for (int r = 0; r < 4; ++r) acc[i][r] = 0.f;

            const float4* hsrc = (const float4*)(g_hA[(t + 1) & 1]);

            // stage chunk into buf; designated lanes wait for the 2 producer
            // blocks whose fragment region this warp copies.
            auto stageH = [&](int chunk, int buf) {
                if (l < 2) {
                    volatile int* cp = g_cnt + chunk * 16 + (w >> 1) + l * 8;
                    while (*cp < t) { }
                }
                __syncwarp();
                const uint32_t d = sb + SM_HB + (uint32_t)buf * 16384u;
                cp_async16(d + (uint32_t)tid * 16u, hsrc + chunk * 1024 + tid);
                cp_async16(d + (uint32_t)(tid + 512) * 16u,
                           hsrc + chunk * 1024 + tid + 512);
            };

            stageH(bid & 7, 0); cp_commit();

            #pragma unroll 1
            for (int i = 0; i < 8; ++i) {
                const int chunk = (i + bid) & 7;
                __syncthreads();   // buffer (i+1)&1 free (last read at iter i-1)
                if (i < 7) {
                    stageH((i + 1 + bid) & 7, (i + 1) & 1);
                    cp_commit(); cp_wait<1>();
                } else cp_wait<0>();
                __syncthreads();   // chunk i data visible

                const float4* hb = (const float4*)(smx + SM_HB + (i & 1) * 16384);
                #pragma unroll
                for (int e = 0; e < 2; ++e) {
                    int ksl = kg * 2 + e;
                    float4 A = hb[ksl * 64 + bh * 32 + l];
                    uint32_t a0 = __float_as_uint(A.x), a1 = __float_as_uint(A.y);
                    uint32_t a2 = __float_as_uint(A.z), a3 = __float_as_uint(A.w);
                    int ks = chunk * 16 + ksl;
                    #pragma unroll
                    for (int nt2 = 0; nt2 < 4; ++nt2) {
                        float2 Bv = *(const float2*)(
                            Vfs + ((size_t)(ks * 4 + nt2) * 32 + l) * 2);
                        uint32_t b0 = __float_as_uint(Bv.x);
                        uint32_t b1 = __float_as_uint(Bv.y);
                        mma8(acc[nt2][0], acc[nt2][1], acc[nt2][2], acc[nt2][3],
                             a0, a1, a2, a3, b0, b1);
                    }
                }
            }
            // partials -> gpart[kg][batch-half bh]
            int r0 = l >> 2;
            float* gp = gpart + kg * 1152 + bh * 576;   // bh*16*36
            #pragma unroll
            for (int nt2 = 0; nt2 < 4; ++nt2) {
                int cb = nt2 * 8 + (l & 3) * 2;
                *(float2*)&gp[r0 * 36 + cb]       = make_float2(acc[nt2][0], acc[nt2][1]);
                *(float2*)&gp[(r0 + 8) * 36 + cb] = make_float2(acc[nt2][2], acc[nt2][3]);
            }
        }
        __syncthreads();

        // overwrite-guard: h(t) replaces h(t-2); all blocks must be >= t.
        // Poll overlaps with gate math below.
        if (tid >= 256 && tid < 256 + NBLK) {
            volatile int* cp = g_cnt + (tid - 256);
            while (*cp < t) __nanosleep(16);
        }

        float hval = 0.f;
        if (tid < 256) {
            float g0 = xg0, g1 = xg1, g2 = xg2, g3 = xg3;
            #pragma unroll
            for (int ks = 0; ks < 8; ++ks) {
                float4 p = *(const float4*)&gpart[ks * 1152 + pb * 36 + pu * 4];
                g0 += p.x; g1 += p.y; g2 += p.z; g3 += p.w;
            }
            float fg = sigmoid_f(g0), ig = sigmoid_f(g1);
            float og = sigmoid_f(g2), gg = tanh_f(g3);
            cr = fg * cr + ig * gg;
            hval = og * tanh_f(cr);
        }
        __syncthreads();   // guard satisfied by all pollers

        if (tid < 256) {
            int mt = pb >> 4, br = pb & 15;
            int lane = (br & 7) * 4 + (pu & 3);
            int wd = (pu < 4) ? ((br & 8) ? 1 : 0) : ((br & 8) ? 3 : 2);
            g_hA[t & 1][((bid * 2 + mt) * 32 + lane) * 4 + wd] = to_tf32(hval);
            __threadfence();
        }
        __syncthreads();
        if (tid == 0) g_cnt[bid] = t + 1;   // publish: h(t) visible

        // deferred (off critical path) output writes
        if (tid < 256) {
            hseq[((size_t)pb * SEQ + t) * HID + hbase + pu] = hval;
            if (t == SEQ - 1) hlast[(size_t)pb * HID + hbase + pu] = hval;
        }
    }
}

// ---------------- launch ----------------
extern "C" void kernel_launch(void* const* d_in, const int* in_sizes, int n_in,
                              void* d_out, int out_size)
{
    const float* x  = (const float*)d_in[0];
    const float* Uf = (const float*)d_in[1];
    const float* Vf = (const float*)d_in[2];
    const float* bf = (const float*)d_in[3];
    const float* Ui = (const float*)d_in[4];
    const float* Vi = (const float*)d_in[5];
    const float* bi = (const float*)d_in[6];
    const float* Uo = (const float*)d_in[7];
    const float* Vo = (const float*)d_in[8];
    const float* bo = (const float*)d_in[9];
    const float* Ug = (const float*)d_in[10];
    const float* Vg = (const float*)d_in[11];
    const float* bg = (const float*)d_in[12];

    float* out   = (float*)d_out;
    float* hlast = out;                 // [32][1024]
    float* hseq  = out + BSZ * HID;     // [32][512][1024]

    void* cn = nullptr;
    cudaGetSymbolAddress(&cn, g_cnt);
    cudaMemsetAsync(cn, 0, NBLK * sizeof(int), 0);

    cudaFuncSetAttribute(gemm_xU_mma, cudaFuncAttributeMaxDynamicSharedMemorySize, PA_SMEM);
    cudaFuncSetAttribute(lstm_mma, cudaFuncAttributeMaxDynamicSharedMemorySize, SMEM_B_BYTES);

    prep<<<416, 256>>>(x, Uf, Ui, Uo, Ug, Vf, Vi, Vo, Vg, bf, bi, bo, bg);
    dim3 ggrid(G4 / 128, (BSZ * SEQ) / 128);   // (32, 128)
    gemm_xU_mma<<<ggrid, 256, PA_SMEM>>>();
    lstm_mma<<<NBLK, 512, SMEM_B_BYTES>>>(hseq, hlast);
}